// round 1
// baseline (speedup 1.0000x reference)
#include <cuda_runtime.h>
#include <math.h>

#define B_  4
#define S_  2048
#define D_  1024
#define H_  16
#define HD_ 64
#define M_  (B_ * S_)   // 8192

// ---------------- scratch (static device memory; no runtime allocation) ----
__device__ float g_Q[M_ * D_];
__device__ float g_K[M_ * D_];
__device__ float g_V[M_ * D_];
__device__ float g_AO[M_ * D_];
__device__ float g_u[M_];
__device__ float g_lam[B_];
__device__ float g_pmrm[S_];

// ---------------- u = ||dx|| / (||x|| + eps) per (b,s) ----------------------
__global__ void __launch_bounds__(256) row_u_kernel(const float* __restrict__ x,
                                                    const float* __restrict__ dx)
{
    const int row = blockIdx.x;
    const float* xr = x  + (size_t)row * D_;
    const float* dr = dx + (size_t)row * D_;
    float sx = 0.f, sd = 0.f;
    for (int c = threadIdx.x; c < D_; c += 256) {
        float a = xr[c]; sx = fmaf(a, a, sx);
        float b = dr[c]; sd = fmaf(b, b, sd);
    }
    __shared__ float shx[32], shd[32];
    int lane = threadIdx.x & 31, wid = threadIdx.x >> 5;
    #pragma unroll
    for (int o = 16; o; o >>= 1) {
        sx += __shfl_xor_sync(0xffffffffu, sx, o);
        sd += __shfl_xor_sync(0xffffffffu, sd, o);
    }
    if (lane == 0) { shx[wid] = sx; shd[wid] = sd; }
    __syncthreads();
    if (wid == 0) {
        sx = (lane < 8) ? shx[lane] : 0.f;
        sd = (lane < 8) ? shd[lane] : 0.f;
        #pragma unroll
        for (int o = 4; o; o >>= 1) {
            sx += __shfl_xor_sync(0xffffffffu, sx, o);
            sd += __shfl_xor_sync(0xffffffffu, sd, o);
        }
        if (lane == 0) g_u[row] = sqrtf(sd) / (sqrtf(sx) + 1e-8f);
    }
}

// ---------------- lam[b] = 10 * exp(-5 * mean_s u) --------------------------
__global__ void __launch_bounds__(256) lam_kernel()
{
    const int b = blockIdx.x;
    float s = 0.f;
    for (int i = threadIdx.x; i < S_; i += 256) s += g_u[b * S_ + i];
    __shared__ float sh[32];
    int lane = threadIdx.x & 31, wid = threadIdx.x >> 5;
    #pragma unroll
    for (int o = 16; o; o >>= 1) s += __shfl_xor_sync(0xffffffffu, s, o);
    if (lane == 0) sh[wid] = s;
    __syncthreads();
    if (wid == 0) {
        s = (lane < 8) ? sh[lane] : 0.f;
        #pragma unroll
        for (int o = 4; o; o >>= 1) s += __shfl_xor_sync(0xffffffffu, s, o);
        if (lane == 0) g_lam[b] = 10.0f * expf(-5.0f * (s / (float)S_));
    }
}

// ---------------- pm_rowmean[q] = mean_k prior_mask[q,k] --------------------
__global__ void __launch_bounds__(256) pmrm_kernel(const float* __restrict__ pm)
{
    const int q = blockIdx.x;
    float s = 0.f;
    for (int k = threadIdx.x; k < S_; k += 256) s += pm[(size_t)q * S_ + k];
    __shared__ float sh[32];
    int lane = threadIdx.x & 31, wid = threadIdx.x >> 5;
    #pragma unroll
    for (int o = 16; o; o >>= 1) s += __shfl_xor_sync(0xffffffffu, s, o);
    if (lane == 0) sh[wid] = s;
    __syncthreads();
    if (wid == 0) {
        s = (lane < 8) ? sh[lane] : 0.f;
        #pragma unroll
        for (int o = 4; o; o >>= 1) s += __shfl_xor_sync(0xffffffffu, s, o);
        if (lane == 0) g_pmrm[q] = s / (float)S_;
    }
}

// ---------------- SGEMM NT: C[m,n] = sum_k A[m,k]*W[n,k] + bias[n] ----------
// 128x128 tile, BK=8, 256 threads, 8x8 per thread. M%128==0, N%128==0, K%8==0.
__global__ void __launch_bounds__(256) sgemm_nt_bias(const float* __restrict__ A,
                                                     const float* __restrict__ W,
                                                     const float* __restrict__ bias,
                                                     float* __restrict__ C,
                                                     int M, int N, int K)
{
    __shared__ float As[8][128];
    __shared__ float Bs[8][128];
    const int t  = threadIdx.x;
    const int tx = t & 15;
    const int ty = t >> 4;
    const size_t aBase = (size_t)blockIdx.y * 128 * K;
    const size_t bBase = (size_t)blockIdx.x * 128 * K;
    const int lrow = t >> 1;
    const int lcol = (t & 1) << 2;

    float acc[8][8];
    #pragma unroll
    for (int i = 0; i < 8; i++)
        #pragma unroll
        for (int j = 0; j < 8; j++) acc[i][j] = 0.f;

    for (int k0 = 0; k0 < K; k0 += 8) {
        float4 av = *(const float4*)(A + aBase + (size_t)lrow * K + k0 + lcol);
        float4 bv = *(const float4*)(W + bBase + (size_t)lrow * K + k0 + lcol);
        __syncthreads();
        As[lcol + 0][lrow] = av.x; As[lcol + 1][lrow] = av.y;
        As[lcol + 2][lrow] = av.z; As[lcol + 3][lrow] = av.w;
        Bs[lcol + 0][lrow] = bv.x; Bs[lcol + 1][lrow] = bv.y;
        Bs[lcol + 2][lrow] = bv.z; Bs[lcol + 3][lrow] = bv.w;
        __syncthreads();
        #pragma unroll
        for (int k = 0; k < 8; k++) {
            float a[8], b[8];
            #pragma unroll
            for (int i = 0; i < 8; i++) a[i] = As[k][(ty << 3) + i];
            #pragma unroll
            for (int j = 0; j < 8; j++) b[j] = Bs[k][(tx << 3) + j];
            #pragma unroll
            for (int i = 0; i < 8; i++)
                #pragma unroll
                for (int j = 0; j < 8; j++)
                    acc[i][j] = fmaf(a[i], b[j], acc[i][j]);
        }
    }

    const int mBase = blockIdx.y * 128 + (ty << 3);
    const int nBase = blockIdx.x * 128 + (tx << 3);
    #pragma unroll
    for (int i = 0; i < 8; i++)
        #pragma unroll
        for (int j = 0; j < 8; j++)
            C[(size_t)(mBase + i) * N + nBase + j] = acc[i][j] + bias[nBase + j];
}

// ---------------- flash attention with bias + clipping ----------------------
// grid (S/64, H, B), 256 threads; 64x64 q/k tiles; online softmax.
__global__ void __launch_bounds__(256) attn_kernel(const float* __restrict__ Q,
                                                   const float* __restrict__ K,
                                                   const float* __restrict__ V,
                                                   const float* __restrict__ pm,
                                                   float* __restrict__ O)
{
    __shared__ float Qs[64][64];   // [r][d]
    __shared__ float KP[64][64];   // K transposed [d][c], later P [r][k]
    __shared__ float Vs[64][64];   // [k][d]

    const int b = blockIdx.z, h = blockIdx.y, qt = blockIdx.x;
    const int t  = threadIdx.x;
    const int tx = t & 15;
    const int ty = t >> 4;
    const float lamv   = g_lam[b];
    const bool  doclip = (lamv > 1.0f);

    const int lr = t >> 2;   // 0..63
    const int ls = t & 3;    // 0..3

    // load Q tile
    const size_t qoff = ((size_t)(b * S_) + (size_t)qt * 64) * D_ + h * HD_;
    #pragma unroll
    for (int i = 0; i < 4; i++) {
        int c = (ls + (i << 2)) << 2;
        float4 v = *(const float4*)(Q + qoff + (size_t)lr * D_ + c);
        Qs[lr][c] = v.x; Qs[lr][c + 1] = v.y; Qs[lr][c + 2] = v.z; Qs[lr][c + 3] = v.w;
    }

    float m[4], l[4], thr[4], acc[4][4];
    #pragma unroll
    for (int i = 0; i < 4; i++) {
        m[i] = -1e30f; l[i] = 0.f;
        thr[i] = lamv * g_pmrm[qt * 64 + (ty << 2) + i];
        #pragma unroll
        for (int j = 0; j < 4; j++) acc[i][j] = 0.f;
    }

    for (int kt = 0; kt < S_ / 64; kt++) {
        __syncthreads();  // prior AV done; Qs visible on first iter
        const size_t koff = ((size_t)(b * S_) + (size_t)kt * 64) * D_ + h * HD_;
        #pragma unroll
        for (int i = 0; i < 4; i++) {
            int c = (ls + (i << 2)) << 2;
            float4 kv = *(const float4*)(K + koff + (size_t)lr * D_ + c);
            KP[c][lr] = kv.x; KP[c + 1][lr] = kv.y; KP[c + 2][lr] = kv.z; KP[c + 3][lr] = kv.w;
            float4 vv = *(const float4*)(V + koff + (size_t)lr * D_ + c);
            *(float4*)&Vs[lr][c] = vv;
        }
        __syncthreads();

        // scores: s[i][j] = sum_d Qs[row][d] * Kt[d][col]
        float s[4][4];
        #pragma unroll
        for (int i = 0; i < 4; i++)
            #pragma unroll
            for (int j = 0; j < 4; j++) s[i][j] = 0.f;
        #pragma unroll 8
        for (int d = 0; d < 64; d++) {
            float qv[4], kv[4];
            #pragma unroll
            for (int i = 0; i < 4; i++) qv[i] = Qs[(ty << 2) + i][d];
            #pragma unroll
            for (int j = 0; j < 4; j++) kv[j] = KP[d][(tx << 2) + j];
            #pragma unroll
            for (int i = 0; i < 4; i++)
                #pragma unroll
                for (int j = 0; j < 4; j++)
                    s[i][j] = fmaf(qv[i], kv[j], s[i][j]);
        }

        // bias + clip
        const float* pmr = pm + (size_t)(qt * 64 + (ty << 2)) * S_ + kt * 64 + (tx << 2);
        #pragma unroll
        for (int i = 0; i < 4; i++) {
            #pragma unroll
            for (int j = 0; j < 4; j++) {
                float Lv = fmaf(lamv, pmr[(size_t)i * S_ + j], s[i][j] * 0.125f);
                if (doclip && Lv < thr[i]) Lv = -1e30f;
                s[i][j] = Lv;
            }
        }

        // online softmax update
        #pragma unroll
        for (int i = 0; i < 4; i++) {
            float mloc = fmaxf(fmaxf(s[i][0], s[i][1]), fmaxf(s[i][2], s[i][3]));
            #pragma unroll
            for (int o = 8; o; o >>= 1)
                mloc = fmaxf(mloc, __shfl_xor_sync(0xffffffffu, mloc, o));
            float mnew  = fmaxf(m[i], mloc);
            float scale = __expf(m[i] - mnew);
            float ps = 0.f;
            #pragma unroll
            for (int j = 0; j < 4; j++) {
                s[i][j] = __expf(s[i][j] - mnew);
                ps += s[i][j];
            }
            #pragma unroll
            for (int o = 8; o; o >>= 1)
                ps += __shfl_xor_sync(0xffffffffu, ps, o);
            l[i] = fmaf(l[i], scale, ps);
            m[i] = mnew;
            #pragma unroll
            for (int j = 0; j < 4; j++) acc[i][j] *= scale;
        }

        __syncthreads();  // done reading KP as K
        #pragma unroll
        for (int i = 0; i < 4; i++)
            #pragma unroll
            for (int j = 0; j < 4; j++)
                KP[(ty << 2) + i][(tx << 2) + j] = s[i][j];
        __syncthreads();

        // AV: acc[i][j] += sum_k P[row][k] * Vs[k][col]
        #pragma unroll 8
        for (int k = 0; k < 64; k++) {
            float pv[4], vv[4];
            #pragma unroll
            for (int i = 0; i < 4; i++) pv[i] = KP[(ty << 2) + i][k];
            #pragma unroll
            for (int j = 0; j < 4; j++) vv[j] = Vs[k][(tx << 2) + j];
            #pragma unroll
            for (int i = 0; i < 4; i++)
                #pragma unroll
                for (int j = 0; j < 4; j++)
                    acc[i][j] = fmaf(pv[i], vv[j], acc[i][j]);
        }
    }

    // write normalized output
    const size_t ooff = ((size_t)(b * S_) + (size_t)qt * 64) * D_ + h * HD_;
    #pragma unroll
    for (int i = 0; i < 4; i++) {
        float inv = 1.0f / l[i];
        #pragma unroll
        for (int j = 0; j < 4; j++)
            O[ooff + (size_t)((ty << 2) + i) * D_ + (tx << 2) + j] = acc[i][j] * inv;
    }
}

// ---------------- launch ----------------------------------------------------
extern "C" void kernel_launch(void* const* d_in, const int* in_sizes, int n_in,
                              void* d_out, int out_size)
{
    const float* x  = (const float*)d_in[0];
    const float* pm = (const float*)d_in[1];
    const float* dx = (const float*)d_in[2];
    const float* wq = (const float*)d_in[3];
    const float* bq = (const float*)d_in[4];
    const float* wk = (const float*)d_in[5];
    const float* bk = (const float*)d_in[6];
    const float* wv = (const float*)d_in[7];
    const float* bv = (const float*)d_in[8];
    const float* wo = (const float*)d_in[9];
    const float* bo = (const float*)d_in[10];
    float* out = (float*)d_out;

    float *gQ, *gK, *gV, *gAO;
    cudaGetSymbolAddress((void**)&gQ,  g_Q);
    cudaGetSymbolAddress((void**)&gK,  g_K);
    cudaGetSymbolAddress((void**)&gV,  g_V);
    cudaGetSymbolAddress((void**)&gAO, g_AO);

    // scalar stats
    row_u_kernel<<<M_, 256>>>(x, dx);
    lam_kernel<<<B_, 256>>>();
    pmrm_kernel<<<S_, 256>>>(pm);

    // QKV projections
    dim3 gg(D_ / 128, M_ / 128);
    sgemm_nt_bias<<<gg, 256>>>(x, wq, bq, gQ, M_, D_, D_);
    sgemm_nt_bias<<<gg, 256>>>(x, wk, bk, gK, M_, D_, D_);
    sgemm_nt_bias<<<gg, 256>>>(x, wv, bv, gV, M_, D_, D_);

    // attention
    dim3 ag(S_ / 64, H_, B_);
    attn_kernel<<<ag, 256>>>(gQ, gK, gV, pm, gAO);

    // output projection
    sgemm_nt_bias<<<gg, 256>>>(gAO, wo, bo, out, M_, D_, D_);
}

// round 3
// speedup vs baseline: 1.5148x; 1.5148x over previous
#include <cuda_runtime.h>
#include <cuda_bf16.h>
#include <math.h>
#include <stdint.h>

#define B_  4
#define S_  2048
#define D_  1024
#define H_  16
#define HD_ 64
#define M_  (B_ * S_)     // 8192
#define KX_ 3072          // extended K for split-bf16 (3 * 1024)
#define NC_ 48            // K chunks of 64

// ---------------- scratch (static device memory) ---------------------------
__device__ float g_Q[M_ * D_];
__device__ float g_K[M_ * D_];
__device__ float g_V[M_ * D_];
__device__ float g_AO[M_ * D_];
__device__ __nv_bfloat16 g_A2[M_ * KX_];          // split activations
__device__ __nv_bfloat16 g_W2[4 * D_ * KX_];      // split weights (q,k,v,o)
__device__ float g_u[M_];
__device__ float g_lam[B_];
__device__ float g_pmrm[S_];

// ---------------- f32x2 packed helpers --------------------------------------
__device__ __forceinline__ uint64_t pk2(float a, float b) {
    uint64_t r; asm("mov.b64 %0, {%1, %2};" : "=l"(r) : "f"(a), "f"(b)); return r;
}
__device__ __forceinline__ void upk2(uint64_t v, float& a, float& b) {
    asm("mov.b64 {%0, %1}, %2;" : "=f"(a), "=f"(b) : "l"(v));
}
__device__ __forceinline__ uint64_t fma2(uint64_t a, uint64_t b, uint64_t c) {
    uint64_t d; asm("fma.rn.f32x2 %0, %1, %2, %3;" : "=l"(d) : "l"(a), "l"(b), "l"(c)); return d;
}
__device__ __forceinline__ uint64_t mul2(uint64_t a, uint64_t b) {
    uint64_t d; asm("mul.rn.f32x2 %0, %1, %2;" : "=l"(d) : "l"(a), "l"(b)); return d;
}

// ---------------- HMMA helpers ----------------------------------------------
__device__ __forceinline__ uint32_t smem_u32(const void* p) {
    uint32_t a;
    asm("{ .reg .u64 t; cvta.to.shared.u64 t, %1; cvt.u32.u64 %0, t; }" : "=r"(a) : "l"(p));
    return a;
}
__device__ __forceinline__ void ldsm4(uint32_t& r0, uint32_t& r1, uint32_t& r2, uint32_t& r3,
                                      uint32_t addr) {
    asm volatile("ldmatrix.sync.aligned.m8n8.x4.shared.b16 {%0,%1,%2,%3}, [%4];"
                 : "=r"(r0), "=r"(r1), "=r"(r2), "=r"(r3) : "r"(addr));
}
__device__ __forceinline__ void mma_bf16(float* c, const uint32_t* a, uint32_t b0, uint32_t b1) {
    asm volatile("mma.sync.aligned.m16n8k16.row.col.f32.bf16.bf16.f32 "
                 "{%0,%1,%2,%3}, {%4,%5,%6,%7}, {%8,%9}, {%0,%1,%2,%3};"
                 : "+f"(c[0]), "+f"(c[1]), "+f"(c[2]), "+f"(c[3])
                 : "r"(a[0]), "r"(a[1]), "r"(a[2]), "r"(a[3]), "r"(b0), "r"(b1));
}
#define CP_ASYNC16(sm, gm) \
    asm volatile("cp.async.cg.shared.global [%0], [%1], 16;" :: "r"(sm), "l"(gm))
#define CP_COMMIT() asm volatile("cp.async.commit_group;")
#define CP_WAIT1()  asm volatile("cp.async.wait_group 1;")
#define CP_WAIT0()  asm volatile("cp.async.wait_group 0;")

// ---------------- u = ||dx|| / (||x|| + eps) per (b,s) ----------------------
__global__ void __launch_bounds__(256) row_u_kernel(const float* __restrict__ x,
                                                    const float* __restrict__ dx)
{
    const int row = blockIdx.x;
    const float* xr = x  + (size_t)row * D_;
    const float* dr = dx + (size_t)row * D_;
    float sx = 0.f, sd = 0.f;
    for (int c = threadIdx.x; c < D_; c += 256) {
        float a = xr[c]; sx = fmaf(a, a, sx);
        float b = dr[c]; sd = fmaf(b, b, sd);
    }
    __shared__ float shx[32], shd[32];
    int lane = threadIdx.x & 31, wid = threadIdx.x >> 5;
    #pragma unroll
    for (int o = 16; o; o >>= 1) {
        sx += __shfl_xor_sync(0xffffffffu, sx, o);
        sd += __shfl_xor_sync(0xffffffffu, sd, o);
    }
    if (lane == 0) { shx[wid] = sx; shd[wid] = sd; }
    __syncthreads();
    if (wid == 0) {
        sx = (lane < 8) ? shx[lane] : 0.f;
        sd = (lane < 8) ? shd[lane] : 0.f;
        #pragma unroll
        for (int o = 4; o; o >>= 1) {
            sx += __shfl_xor_sync(0xffffffffu, sx, o);
            sd += __shfl_xor_sync(0xffffffffu, sd, o);
        }
        if (lane == 0) g_u[row] = sqrtf(sd) / (sqrtf(sx) + 1e-8f);
    }
}

__global__ void __launch_bounds__(256) lam_kernel()
{
    const int b = blockIdx.x;
    float s = 0.f;
    for (int i = threadIdx.x; i < S_; i += 256) s += g_u[b * S_ + i];
    __shared__ float sh[32];
    int lane = threadIdx.x & 31, wid = threadIdx.x >> 5;
    #pragma unroll
    for (int o = 16; o; o >>= 1) s += __shfl_xor_sync(0xffffffffu, s, o);
    if (lane == 0) sh[wid] = s;
    __syncthreads();
    if (wid == 0) {
        s = (lane < 8) ? sh[lane] : 0.f;
        #pragma unroll
        for (int o = 4; o; o >>= 1) s += __shfl_xor_sync(0xffffffffu, s, o);
        if (lane == 0) g_lam[b] = 10.0f * expf(-5.0f * (s / (float)S_));
    }
}

__global__ void __launch_bounds__(256) pmrm_kernel(const float* __restrict__ pm)
{
    const int q = blockIdx.x;
    float s = 0.f;
    for (int k = threadIdx.x; k < S_; k += 256) s += pm[(size_t)q * S_ + k];
    __shared__ float sh[32];
    int lane = threadIdx.x & 31, wid = threadIdx.x >> 5;
    #pragma unroll
    for (int o = 16; o; o >>= 1) s += __shfl_xor_sync(0xffffffffu, s, o);
    if (lane == 0) sh[wid] = s;
    __syncthreads();
    if (wid == 0) {
        s = (lane < 8) ? sh[lane] : 0.f;
        #pragma unroll
        for (int o = 4; o; o >>= 1) s += __shfl_xor_sync(0xffffffffu, s, o);
        if (lane == 0) g_pmrm[q] = s / (float)S_;
    }
}

// ---------------- split fp32 -> extended-K bf16 -----------------------------
// mode 0 (activations): [hi | lo | hi]; mode 1 (weights): [hi | hi | lo]
template<int MODE>
__global__ void __launch_bounds__(256) split_kernel(const float* __restrict__ src,
                                                    __nv_bfloat16* __restrict__ dst)
{
    const int r = blockIdx.x;
    const int c = threadIdx.x * 4;
    float4 v = *(const float4*)(src + (size_t)r * D_ + c);
    __nv_bfloat16 h0 = __float2bfloat16_rn(v.x);
    __nv_bfloat16 h1 = __float2bfloat16_rn(v.y);
    __nv_bfloat16 h2 = __float2bfloat16_rn(v.z);
    __nv_bfloat16 h3 = __float2bfloat16_rn(v.w);
    __nv_bfloat16 l0 = __float2bfloat16_rn(v.x - __bfloat162float(h0));
    __nv_bfloat16 l1 = __float2bfloat16_rn(v.y - __bfloat162float(h1));
    __nv_bfloat16 l2 = __float2bfloat16_rn(v.z - __bfloat162float(h2));
    __nv_bfloat16 l3 = __float2bfloat16_rn(v.w - __bfloat162float(h3));
    __nv_bfloat162 hA = {h0, h1}, hB = {h2, h3};
    __nv_bfloat162 lA = {l0, l1}, lB = {l2, l3};
    __nv_bfloat16* d0 = dst + (size_t)r * KX_ + c;
    if (MODE == 0) {  // hi, lo, hi
        *(__nv_bfloat162*)(d0)            = hA; *(__nv_bfloat162*)(d0 + 2)        = hB;
        *(__nv_bfloat162*)(d0 + D_)       = lA; *(__nv_bfloat162*)(d0 + D_ + 2)   = lB;
        *(__nv_bfloat162*)(d0 + 2*D_)     = hA; *(__nv_bfloat162*)(d0 + 2*D_ + 2) = hB;
    } else {          // hi, hi, lo
        *(__nv_bfloat162*)(d0)            = hA; *(__nv_bfloat162*)(d0 + 2)        = hB;
        *(__nv_bfloat162*)(d0 + D_)       = hA; *(__nv_bfloat162*)(d0 + D_ + 2)   = hB;
        *(__nv_bfloat162*)(d0 + 2*D_)     = lA; *(__nv_bfloat162*)(d0 + 2*D_ + 2) = lB;
    }
}

// ---------------- HMMA GEMM: C[M,N] = A2 @ W2^T + bias ----------------------
// 128x128 CTA tile, BK=64 bf16, 256 threads (8 warps, 4x2 warp grid, 32x64/warp)
// SMEM tiles 128 rows x 128B, XOR-swizzled; cp.async double-buffered.
#define GT_TILE 16384   // one 128x64 bf16 tile
#define GT_TOT  (4 * GT_TILE)

__global__ void __launch_bounds__(256) gemm_mma(const __nv_bfloat16* __restrict__ A2,
                                                const __nv_bfloat16* __restrict__ W2base,
                                                const float* __restrict__ b0,
                                                const float* __restrict__ b1,
                                                const float* __restrict__ b2,
                                                float* __restrict__ c0,
                                                float* __restrict__ c1,
                                                float* __restrict__ c2)
{
    extern __shared__ char smem[];
    const uint32_t sA = smem_u32(smem);           // A buffers: sA, sA+GT_TILE
    const uint32_t sB = sA + 2 * GT_TILE;         // B buffers

    const int t    = threadIdx.x;
    const int lane = t & 31;
    const int w    = t >> 5;
    const int z    = blockIdx.z;
    const __nv_bfloat16* W2 = W2base + (size_t)z * D_ * KX_;
    const float* bias = (z == 0) ? b0 : (z == 1) ? b1 : b2;
    float* C = (z == 0) ? c0 : (z == 1) ? c1 : c2;

    const int wm = (w & 3) * 32;   // warp m offset in tile
    const int wn = (w >> 2) * 64;  // warp n offset in tile

    // -------- global/smem addresses for cp.async (4 rows each of A, B) ------
    const int ch   = t & 7;               // 16B chunk within 128B row
    const int rb   = t >> 3;              // base row (0..31)
    const int swch = ch ^ (rb & 7);       // swizzled chunk (row&7 invariant under +32)
    const __nv_bfloat16* gAp[4];
    const __nv_bfloat16* gBp[4];
    uint32_t smA[4], smB[4];
    #pragma unroll
    for (int p = 0; p < 4; p++) {
        int row = rb + p * 32;
        gAp[p] = A2 + ((size_t)blockIdx.y * 128 + row) * KX_ + ch * 8;
        gBp[p] = W2 + ((size_t)blockIdx.x * 128 + row) * KX_ + ch * 8;
        smA[p] = sA + row * 128 + swch * 16;
        smB[p] = sB + row * 128 + swch * 16;
    }

    float acc[2][8][4];
    #pragma unroll
    for (int i = 0; i < 2; i++)
        #pragma unroll
        for (int j = 0; j < 8; j++)
            #pragma unroll
            for (int k = 0; k < 4; k++) acc[i][j][k] = 0.f;

    // prologue: load chunk 0 into buffer 0
    #pragma unroll
    for (int p = 0; p < 4; p++) { CP_ASYNC16(smA[p], gAp[p]); CP_ASYNC16(smB[p], gBp[p]); }
    CP_COMMIT();

    // ldmatrix lane addressing (row/chunk parts)
    const int lrow = lane & 15;       // row within 16x16
    const int lhalf = lane >> 4;      // 0/1 -> k chunk select

    for (int kc = 0; kc < NC_; kc++) {
        const int b = kc & 1;
        if (kc + 1 < NC_) {
            const int nb = (kc + 1) & 1;
            const size_t goff = (size_t)(kc + 1) * 64;
            #pragma unroll
            for (int p = 0; p < 4; p++) {
                CP_ASYNC16(smA[p] + nb * GT_TILE, gAp[p] + goff);
                CP_ASYNC16(smB[p] + nb * GT_TILE, gBp[p] + goff);
            }
            CP_COMMIT();
            CP_WAIT1();
        } else {
            CP_WAIT0();
        }
        __syncthreads();

        const uint32_t bA = sA + b * GT_TILE;
        const uint32_t bB = sB + b * GT_TILE;

        #pragma unroll
        for (int ks = 0; ks < 4; ks++) {
            // A fragments: 2 x (16x16)
            uint32_t af[2][4];
            #pragma unroll
            for (int mi = 0; mi < 2; mi++) {
                int row = wm + mi * 16 + lrow;
                int chk = (ks * 2 + lhalf) ^ (row & 7);
                ldsm4(af[mi][0], af[mi][1], af[mi][2], af[mi][3],
                      bA + row * 128 + chk * 16);
            }
            // B fragments: 4 x (n16 x k16) -> 8 n-tiles
            #pragma unroll
            for (int nj = 0; nj < 4; nj++) {
                uint32_t r0, r1, r2, r3;
                int row = wn + nj * 16 + lrow;
                int chk = (ks * 2 + lhalf) ^ (row & 7);
                ldsm4(r0, r1, r2, r3, bB + row * 128 + chk * 16);
                #pragma unroll
                for (int mi = 0; mi < 2; mi++) {
                    mma_bf16(acc[mi][nj * 2 + 0], af[mi], r0, r2);
                    mma_bf16(acc[mi][nj * 2 + 1], af[mi], r1, r3);
                }
            }
        }
        __syncthreads();
    }

    // -------- epilogue: bias + store ----------------------------------------
    const int tr = lane >> 2;          // 0..7
    const int tc = (lane & 3) * 2;     // 0,2,4,6
    const int gy = blockIdx.y * 128;
    const int gx = blockIdx.x * 128;
    #pragma unroll
    for (int mi = 0; mi < 2; mi++) {
        #pragma unroll
        for (int nj = 0; nj < 8; nj++) {
            int col = gx + wn + nj * 8 + tc;
            float2 bv = *(const float2*)(bias + col);
            int row0 = gy + wm + mi * 16 + tr;
            float2 o0 = { acc[mi][nj][0] + bv.x, acc[mi][nj][1] + bv.y };
            float2 o1 = { acc[mi][nj][2] + bv.x, acc[mi][nj][3] + bv.y };
            *(float2*)(C + (size_t)row0 * D_ + col)       = o0;
            *(float2*)(C + (size_t)(row0 + 8) * D_ + col) = o1;
        }
    }
}

// ---------------- flash attention with bias + clipping (f32x2 math) ---------
__global__ void __launch_bounds__(256) attn_kernel(const float* __restrict__ Q,
                                                   const float* __restrict__ K,
                                                   const float* __restrict__ V,
                                                   const float* __restrict__ pm,
                                                   float* __restrict__ O)
{
    __shared__ float Qs[64][64];
    __shared__ float KP[64][64];
    __shared__ float Vs[64][64];

    const int b = blockIdx.z, h = blockIdx.y, qt = blockIdx.x;
    const int t  = threadIdx.x;
    const int tx = t & 15;
    const int ty = t >> 4;
    const float lamv   = g_lam[b];
    const bool  doclip = (lamv > 1.0f);

    const int lr = t >> 2;
    const int ls = t & 3;

    const size_t qoff = ((size_t)(b * S_) + (size_t)qt * 64) * D_ + h * HD_;
    #pragma unroll
    for (int i = 0; i < 4; i++) {
        int c = (ls + (i << 2)) << 2;
        float4 v = *(const float4*)(Q + qoff + (size_t)lr * D_ + c);
        Qs[lr][c] = v.x; Qs[lr][c + 1] = v.y; Qs[lr][c + 2] = v.z; Qs[lr][c + 3] = v.w;
    }

    float m[4], l[4], thr[4];
    uint64_t acc2[4][2];
    #pragma unroll
    for (int i = 0; i < 4; i++) {
        m[i] = -1e30f; l[i] = 0.f;
        thr[i] = lamv * g_pmrm[qt * 64 + (ty << 2) + i];
        acc2[i][0] = 0ull; acc2[i][1] = 0ull;
    }

    for (int kt = 0; kt < S_ / 64; kt++) {
        __syncthreads();
        const size_t koff = ((size_t)(b * S_) + (size_t)kt * 64) * D_ + h * HD_;
        #pragma unroll
        for (int i = 0; i < 4; i++) {
            int c = (ls + (i << 2)) << 2;
            float4 kv = *(const float4*)(K + koff + (size_t)lr * D_ + c);
            KP[c][lr] = kv.x; KP[c + 1][lr] = kv.y; KP[c + 2][lr] = kv.z; KP[c + 3][lr] = kv.w;
            float4 vv = *(const float4*)(V + koff + (size_t)lr * D_ + c);
            *(float4*)&Vs[lr][c] = vv;
        }
        __syncthreads();

        // scores via packed fp32x2
        uint64_t s2[4][2];
        #pragma unroll
        for (int i = 0; i < 4; i++) { s2[i][0] = 0ull; s2[i][1] = 0ull; }
        #pragma unroll 8
        for (int d = 0; d < 64; d++) {
            const float* kr = &KP[d][tx << 2];
            uint64_t k0 = *(const uint64_t*)kr;
            uint64_t k1 = *(const uint64_t*)(kr + 2);
            #pragma unroll
            for (int i = 0; i < 4; i++) {
                float q = Qs[(ty << 2) + i][d];
                uint64_t qq = pk2(q, q);
                s2[i][0] = fma2(qq, k0, s2[i][0]);
                s2[i][1] = fma2(qq, k1, s2[i][1]);
            }
        }
        float s[4][4];
        #pragma unroll
        for (int i = 0; i < 4; i++) {
            upk2(s2[i][0], s[i][0], s[i][1]);
            upk2(s2[i][1], s[i][2], s[i][3]);
        }

        // bias + clip
        const float* pmr = pm + (size_t)(qt * 64 + (ty << 2)) * S_ + kt * 64 + (tx << 2);
        #pragma unroll
        for (int i = 0; i < 4; i++) {
            #pragma unroll
            for (int j = 0; j < 4; j++) {
                float Lv = fmaf(lamv, pmr[(size_t)i * S_ + j], s[i][j] * 0.125f);
                if (doclip && Lv < thr[i]) Lv = -1e30f;
                s[i][j] = Lv;
            }
        }

        // online softmax
        #pragma unroll
        for (int i = 0; i < 4; i++) {
            float mloc = fmaxf(fmaxf(s[i][0], s[i][1]), fmaxf(s[i][2], s[i][3]));
            #pragma unroll
            for (int o = 8; o; o >>= 1)
                mloc = fmaxf(mloc, __shfl_xor_sync(0xffffffffu, mloc, o));
            float mnew  = fmaxf(m[i], mloc);
            float scale = __expf(m[i] - mnew);
            float ps = 0.f;
            #pragma unroll
            for (int j = 0; j < 4; j++) {
                s[i][j] = __expf(s[i][j] - mnew);
                ps += s[i][j];
            }
            #pragma unroll
            for (int o = 8; o; o >>= 1)
                ps += __shfl_xor_sync(0xffffffffu, ps, o);
            l[i] = fmaf(l[i], scale, ps);
            m[i] = mnew;
            uint64_t sc2 = pk2(scale, scale);
            acc2[i][0] = mul2(acc2[i][0], sc2);
            acc2[i][1] = mul2(acc2[i][1], sc2);
        }

        __syncthreads();
        #pragma unroll
        for (int i = 0; i < 4; i++)
            #pragma unroll
            for (int j = 0; j < 4; j++)
                KP[(ty << 2) + i][(tx << 2) + j] = s[i][j];
        __syncthreads();

        // AV via packed fp32x2
        #pragma unroll 8
        for (int k = 0; k < 64; k++) {
            const float* vr = &Vs[k][tx << 2];
            uint64_t v0 = *(const uint64_t*)vr;
            uint64_t v1 = *(const uint64_t*)(vr + 2);
            #pragma unroll
            for (int i = 0; i < 4; i++) {
                float p = KP[(ty << 2) + i][k];
                uint64_t pp = pk2(p, p);
                acc2[i][0] = fma2(pp, v0, acc2[i][0]);
                acc2[i][1] = fma2(pp, v1, acc2[i][1]);
            }
        }
    }

    const size_t ooff = ((size_t)(b * S_) + (size_t)qt * 64) * D_ + h * HD_;
    #pragma unroll
    for (int i = 0; i < 4; i++) {
        float inv = 1.0f / l[i];
        float a0, a1, a2, a3;
        upk2(acc2[i][0], a0, a1);
        upk2(acc2[i][1], a2, a3);
        float* orow = O + ooff + (size_t)((ty << 2) + i) * D_ + (tx << 2);
        orow[0] = a0 * inv; orow[1] = a1 * inv; orow[2] = a2 * inv; orow[3] = a3 * inv;
    }
}

// ---------------- launch ----------------------------------------------------
extern "C" void kernel_launch(void* const* d_in, const int* in_sizes, int n_in,
                              void* d_out, int out_size)
{
    const float* x  = (const float*)d_in[0];
    const float* pm = (const float*)d_in[1];
    const float* dx = (const float*)d_in[2];
    const float* wq = (const float*)d_in[3];
    const float* bq = (const float*)d_in[4];
    const float* wk = (const float*)d_in[5];
    const float* bk = (const float*)d_in[6];
    const float* wv = (const float*)d_in[7];
    const float* bv = (const float*)d_in[8];
    const float* wo = (const float*)d_in[9];
    const float* bo = (const float*)d_in[10];
    float* out = (float*)d_out;

    float *gQ, *gK, *gV, *gAO;
    __nv_bfloat16 *gA2, *gW2;
    cudaGetSymbolAddress((void**)&gQ,  g_Q);
    cudaGetSymbolAddress((void**)&gK,  g_K);
    cudaGetSymbolAddress((void**)&gV,  g_V);
    cudaGetSymbolAddress((void**)&gAO, g_AO);
    cudaGetSymbolAddress((void**)&gA2, g_A2);
    cudaGetSymbolAddress((void**)&gW2, g_W2);

    cudaFuncSetAttribute(gemm_mma, cudaFuncAttributeMaxDynamicSharedMemorySize, GT_TOT);

    // scalar stats
    row_u_kernel<<<M_, 256>>>(x, dx);
    lam_kernel<<<B_, 256>>>();
    pmrm_kernel<<<S_, 256>>>(pm);

    // split inputs to extended-K bf16
    split_kernel<0><<<M_, 256>>>(x, gA2);
    split_kernel<1><<<D_, 256>>>(wq, gW2 + 0 * (size_t)D_ * KX_);
    split_kernel<1><<<D_, 256>>>(wk, gW2 + 1 * (size_t)D_ * KX_);
    split_kernel<1><<<D_, 256>>>(wv, gW2 + 2 * (size_t)D_ * KX_);
    split_kernel<1><<<D_, 256>>>(wo, gW2 + 3 * (size_t)D_ * KX_);

    // fused QKV projection (HMMA tensor cores)
    dim3 gqkv(D_ / 128, M_ / 128, 3);
    gemm_mma<<<gqkv, 256, GT_TOT>>>(gA2, gW2, bq, bk, bv, gQ, gK, gV);

    // attention
    dim3 ag(S_ / 64, H_, B_);
    attn_kernel<<<ag, 256>>>(gQ, gK, gV, pm, gAO);

    // output projection
    split_kernel<0><<<M_, 256>>>(gAO, gA2);
    dim3 go(D_ / 128, M_ / 128, 1);
    gemm_mma<<<go, 256, GT_TOT>>>(gA2, gW2 + 3 * (size_t)D_ * KX_, bo, bo, bo, out, out, out);
}